// round 16
// baseline (speedup 1.0000x reference)
#include <cuda_runtime.h>
#include <cuda_bf16.h>
#include <cuda_fp16.h>
#include <cstdint>

#define Bn  4
#define Qn  2048
#define Kn  2048
#define Dn  1024
#define Hn  16
#define DHn 64
#define BHn (Bn*Hn)

// Q pre-scale: 0.125 * log2(e)  (softmax scale + exp2-domain fold)
#define QSCALE 0.18033688011112042f
#define ATTN_BIAS (-4.0f)
#define MASK_FILL (-80.0f)
#define ONES_H2 0x3C003C00u

// ---------------------------------------------------------------------------
// Scratch (__device__ globals; cudaMalloc is forbidden)
// ---------------------------------------------------------------------------
__device__ __half g_qhi[(size_t)BHn*Qn*DHn];   // Q pre-scaled by QSCALE
__device__ __half g_qlo[(size_t)BHn*Qn*DHn];
__device__ __half g_khi[(size_t)BHn*Kn*DHn];   // K rounded (no lo)
__device__ __half g_vh [(size_t)BHn*Kn*DHn];

__device__ uint32_t g_mbits[(size_t)Bn*Qn*64];

__device__ __half g_xhi[(size_t)8192*1024];
__device__ __half g_xlo[(size_t)8192*1024];
__device__ __half g_ohi[(size_t)8192*1024];        // attn out split (b,q,h*64+d)
__device__ __half g_olo[(size_t)8192*1024];
__device__ __half g_wt [(size_t)3072*1024];        // W_{q,k,v}^T [n][k], fp16
__device__ __half g_wot[(size_t)1024*1024];        // Wo^T [n][k], fp16

// ---------------------------------------------------------------------------
// helpers
// ---------------------------------------------------------------------------
__device__ __forceinline__ uint32_t smem_u32(const void* p) {
    uint32_t a;
    asm("{ .reg .u64 t; cvta.to.shared.u64 t, %1; cvt.u32.u64 %0, t; }"
        : "=r"(a) : "l"(p));
    return a;
}
__device__ __forceinline__ uint32_t h2_as_u32(__half2 v) {
    return *reinterpret_cast<uint32_t*>(&v);
}

#define SMEM_SWIZZLE_128B(byte_offset) \
    ((byte_offset) ^ (((byte_offset) >> 3) & 0x70))

__device__ __forceinline__ void cp_async16(uint32_t s_dst, const void* g_src) {
    asm volatile("cp.async.cg.shared.global [%0], [%1], 16;"
                 :: "r"(s_dst), "l"(g_src));
}
#define CP_COMMIT()  asm volatile("cp.async.commit_group;" ::: "memory")
#define CP_WAIT1()   asm volatile("cp.async.wait_group 1;" ::: "memory")
#define CP_WAIT2()   asm volatile("cp.async.wait_group 2;" ::: "memory")

#define BARH(id) asm volatile("bar.sync %0, 128;" :: "r"(id) : "memory")

__device__ __forceinline__ void ldmx4(uint32_t* r, uint32_t addr) {
    asm volatile("ldmatrix.sync.aligned.m8n8.x4.shared.b16 {%0,%1,%2,%3}, [%4];"
                 : "=r"(r[0]), "=r"(r[1]), "=r"(r[2]), "=r"(r[3]) : "r"(addr));
}
__device__ __forceinline__ void ldmx4t(uint32_t* r, uint32_t addr) {
    asm volatile("ldmatrix.sync.aligned.m8n8.x4.trans.shared.b16 {%0,%1,%2,%3}, [%4];"
                 : "=r"(r[0]), "=r"(r[1]), "=r"(r[2]), "=r"(r[3]) : "r"(addr));
}

__device__ __forceinline__ void mma16816h(float* c, const uint32_t* a,
                                          uint32_t b0, uint32_t b1) {
    asm volatile(
        "mma.sync.aligned.m16n8k16.row.col.f32.f16.f16.f32 "
        "{%0,%1,%2,%3}, {%4,%5,%6,%7}, {%8,%9}, {%0,%1,%2,%3};"
        : "+f"(c[0]), "+f"(c[1]), "+f"(c[2]), "+f"(c[3])
        : "r"(a[0]), "r"(a[1]), "r"(a[2]), "r"(a[3]), "r"(b0), "r"(b1));
}

// fast exp2 (FFMA-only, rel err ~2.4e-6); caller guarantees t >= -80
__device__ __forceinline__ float fexp2(float t) {
    int i = __float2int_rn(t);
    float f = t - (float)i;
    float p = 1.3333558146e-3f;
    p = fmaf(p, f, 9.6181291057e-3f);
    p = fmaf(p, f, 5.5504108664e-2f);
    p = fmaf(p, f, 2.4022650696e-1f);
    p = fmaf(p, f, 6.9314718056e-1f);
    p = fmaf(p, f, 1.0f);
    return p * __int_as_float((i + 127) << 23);
}

// cp.async a 128-row x 128-byte tile into SW128 smem (256 threads)
__device__ __forceinline__ void cp_tile128(uint32_t s_dst, const void* gbase,
                                           size_t ld_bytes, int tid) {
    const char* g = (const char*)gbase;
    #pragma unroll
    for (int i = 0; i < 4; i++) {
        int f = tid + 256*i;
        int row = f >> 3;
        int c16 = f & 7;
        uint32_t off = SMEM_SWIZZLE_128B((uint32_t)(row*128 + c16*16));
        cp_async16(s_dst + off, g + (size_t)row*ld_bytes + c16*16);
    }
}
// cp.async a 64-row x 128-byte tile, 128 threads (one half-CTA)
__device__ __forceinline__ void cp_tile64h(uint32_t s_dst, const void* gbase,
                                           int htid) {
    const char* g = (const char*)gbase;
    #pragma unroll
    for (int i = 0; i < 4; i++) {
        int f = htid + 128*i;     // 0..511
        int row = f >> 3;
        int c16 = f & 7;
        uint32_t off = SMEM_SWIZZLE_128B((uint32_t)(row*128 + c16*16));
        cp_async16(s_dst + off, g + (size_t)row*128 + c16*16);
    }
}

// ---------------------------------------------------------------------------
// Merged prep kernel: split x, transpose+round weights, pack mask bits.
// grid.x = 8192 (split_x) + 2048 (pack_mask) + 4096 (conv_w) = 14336
// ---------------------------------------------------------------------------
__global__ void prep_all(const float* __restrict__ x,
                         const int*   __restrict__ mask,
                         const float* __restrict__ Wq,
                         const float* __restrict__ Wk,
                         const float* __restrict__ Wv,
                         const float* __restrict__ Wo) {
    int bx = blockIdx.x;
    if (bx < 8192) {
        // split x -> fp16 hi/lo
        size_t idx = ((size_t)bx * 256 + threadIdx.x) * 4;
        float4 v = *(const float4*)(x + idx);
        float a[4] = {v.x, v.y, v.z, v.w};
        __half h[4], l[4];
        #pragma unroll
        for (int i = 0; i < 4; i++) {
            h[i] = __float2half_rn(a[i]);
            l[i] = __float2half_rn(a[i] - __half2float(h[i]));
        }
        *(uint2*)(g_xhi + idx) = *(uint2*)h;
        *(uint2*)(g_xlo + idx) = *(uint2*)l;
    } else if (bx < 10240) {
        // pack mask bits via ballot: one warp packs 1024 ints
        int warp = (bx - 8192) * 8 + (threadIdx.x >> 5);
        int lane = threadIdx.x & 31;
        size_t base = (size_t)warp * 1024;
        #pragma unroll 4
        for (int r = 0; r < 32; r++) {
            int v = mask[base + r*32 + lane];
            unsigned bits = __ballot_sync(0xffffffffu, v != 0);
            if (lane == 0) g_mbits[(size_t)warp*32 + r] = bits;
        }
    } else {
        // transpose + round one 32x32 weight tile
        __shared__ float T[32][33];
        int id = bx - 10240;
        int z = id >> 10;
        int rem = id & 1023;
        int n0 = (rem & 31) * 32, k0 = (rem >> 5) * 32;
        const float* src;
        __half* dh;
        if      (z == 0) { src = Wq; dh = g_wt; }
        else if (z == 1) { src = Wk; dh = g_wt + 1024*1024; }
        else if (z == 2) { src = Wv; dh = g_wt + 2048*1024; }
        else             { src = Wo; dh = g_wot; }
        int tx = threadIdx.x & 31, ty = threadIdx.x >> 5;
        #pragma unroll
        for (int i = 0; i < 4; i++)
            T[ty + 8*i][tx] = src[(size_t)(k0 + ty + 8*i) * 1024 + n0 + tx];
        __syncthreads();
        #pragma unroll
        for (int i = 0; i < 4; i++) {
            int n = n0 + ty + 8*i, k = k0 + tx;
            dh[(size_t)n*1024 + k] = __float2half_rn(T[tx][ty + 8*i]);
        }
    }
}

// ---------------------------------------------------------------------------
// mma.sync 2-product split-fp16 GEMM (unchanged from R15 best)
// ---------------------------------------------------------------------------
#define GSTG 49152
#define GEMM_SMEM_BYTES (2*GSTG)

struct GemmAcc { float a[4][4][4]; };

__device__ __forceinline__ void gemm_issue_stage(uint32_t sbuf,
                                                 const __half* Ahi,
                                                 const __half* Alo,
                                                 const __half* B,
                                                 int k0, int tid) {
    cp_tile128(sbuf,           Ahi + k0, 2048, tid);
    cp_tile128(sbuf + 16384,   Alo + k0, 2048, tid);
    cp_tile128(sbuf + 32768,   B   + k0, 2048, tid);
}

__device__ __forceinline__ void gemm_mainloop_mma(uint32_t sb, GemmAcc& A,
                                                  const __half* Ahi,
                                                  const __half* Alo,
                                                  const __half* B,
                                                  int tid) {
    const int wid  = tid >> 5, lane = tid & 31;
    const int mw   = wid & 1, nw = wid >> 1;
    const uint32_t lrow  = lane & 15;
    const uint32_t lkoff = (lane >> 4) * 16;

    #pragma unroll
    for (int mi = 0; mi < 4; mi++)
        #pragma unroll
        for (int ni = 0; ni < 4; ni++)
            #pragma unroll
            for (int j = 0; j < 4; j++) A.a[mi][ni][j] = 0.f;

    gemm_issue_stage(sb,        Ahi, Alo, B, 0,  tid);
    CP_COMMIT();
    gemm_issue_stage(sb + GSTG, Ahi, Alo, B, 64, tid);
    CP_COMMIT();

    for (int st = 0; st < 16; st++) {
        CP_WAIT1();
        __syncthreads();

        const uint32_t sbuf = sb + (st & 1)*GSTG;
        const uint32_t sAh = sbuf, sAl = sbuf + 16384, sB = sbuf + 32768;

        #pragma unroll
        for (int ks = 0; ks < 4; ks++) {
            const uint32_t kb = ks*32 + lkoff;

            uint32_t ah[4][4];
            #pragma unroll
            for (int mi = 0; mi < 4; mi++)
                ldmx4(ah[mi], sAh + SMEM_SWIZZLE_128B(
                      (uint32_t)((mw*64 + mi*16 + lrow)*128) + kb));
            uint32_t bh[2][4];
            #pragma unroll
            for (int np = 0; np < 2; np++)
                ldmx4(bh[np], sB + SMEM_SWIZZLE_128B(
                      (uint32_t)((nw*32 + np*16 + lrow)*128) + kb));

            #pragma unroll
            for (int mi = 0; mi < 4; mi++)
                #pragma unroll
                for (int ni = 0; ni < 4; ni++) {
                    int np = ni >> 1, s = ni & 1;
                    mma16816h(A.a[mi][ni], ah[mi], bh[np][s], bh[np][s+2]);
                }

            uint32_t al[4][4];
            #pragma unroll
            for (int mi = 0; mi < 4; mi++)
                ldmx4(al[mi], sAl + SMEM_SWIZZLE_128B(
                      (uint32_t)((mw*64 + mi*16 + lrow)*128) + kb));
            #pragma unroll
            for (int mi = 0; mi < 4; mi++)
                #pragma unroll
                for (int ni = 0; ni < 4; ni++) {
                    int np = ni >> 1, s = ni & 1;
                    mma16816h(A.a[mi][ni], al[mi], bh[np][s], bh[np][s+2]);
                }
        }
        __syncthreads();

        if (st + 2 < 16)
            gemm_issue_stage(sb + (st & 1)*GSTG, Ahi, Alo, B, (st + 2)*64, tid);
        CP_COMMIT();
    }
}

__global__ __launch_bounds__(256, 2)
void qkv_gemm_mma() {
    extern __shared__ char smem[];
    uint32_t sb = smem_u32(smem);
    int tid = threadIdx.x, lane = tid & 31, wid = tid >> 5;
    int mw = wid & 1, nw = wid >> 1;
    int n_base = blockIdx.x * 128;
    int m0 = blockIdx.y * 128;

    int kind;                      // 0=Q (scaled, hi/lo), 1=K (rounded), 2=V
    if      (n_base < 1024) kind = 0;
    else if (n_base < 2048) kind = 1;
    else                    kind = 2;

    GemmAcc acc;
    gemm_mainloop_mma(sb, acc,
                      g_xhi + (size_t)m0*1024, g_xlo + (size_t)m0*1024,
                      g_wt + (size_t)n_base*1024, tid);

    int col_base = n_base & 1023;
    int g = lane >> 2, tg = lane & 3;
    #pragma unroll
    for (int mi = 0; mi < 4; mi++) {
        #pragma unroll
        for (int ni = 0; ni < 4; ni++) {
            int col = col_base + nw*32 + ni*8 + tg*2;
            int h = col >> 6, d = col & 63;
            #pragma unroll
            for (int half_ = 0; half_ < 2; half_++) {
                int m = m0 + mw*64 + mi*16 + g + half_*8;
                int bb = m >> 11, qp = m & 2047;
                float vx = acc.a[mi][ni][half_*2];
                float vy = acc.a[mi][ni][half_*2+1];
                size_t idx = (((size_t)(bb*Hn + h))*Qn + qp)*DHn + d;
                if (kind == 0) {   // fold softmax scale + log2e into Q
                    vx *= QSCALE; vy *= QSCALE;
                    __half hx = __float2half_rn(vx), hy = __float2half_rn(vy);
                    __half lx = __float2half_rn(vx - __half2float(hx));
                    __half ly = __float2half_rn(vy - __half2float(hy));
                    *(__half2*)&g_qhi[idx] = __halves2half2(hx, hy);
                    *(__half2*)&g_qlo[idx] = __halves2half2(lx, ly);
                } else {
                    __half2 hh = __halves2half2(__float2half_rn(vx),
                                                __float2half_rn(vy));
                    if (kind == 2) *(__half2*)&g_vh[idx]  = hh;
                    else           *(__half2*)&g_khi[idx] = hh;
                }
            }
        }
    }
}

__global__ __launch_bounds__(256, 2)
void out_gemm_mma(const float* __restrict__ bo, float* __restrict__ out) {
    extern __shared__ char smem[];
    uint32_t sb = smem_u32(smem);
    int tid = threadIdx.x, lane = tid & 31, wid = tid >> 5;
    int mw = wid & 1, nw = wid >> 1;
    int n_base = blockIdx.x * 128;
    int m0 = blockIdx.y * 128;

    GemmAcc acc;
    gemm_mainloop_mma(sb, acc,
                      g_ohi + (size_t)m0*1024, g_olo + (size_t)m0*1024,
                      g_wot + (size_t)n_base*1024, tid);

    int g = lane >> 2, tg = lane & 3;
    #pragma unroll
    for (int ni = 0; ni < 4; ni++) {
        int n = n_base + nw*32 + ni*8 + tg*2;
        float2 bias = *(const float2*)&bo[n];
        #pragma unroll
        for (int mi = 0; mi < 4; mi++) {
            #pragma unroll
            for (int half_ = 0; half_ < 2; half_++) {
                int m = m0 + mw*64 + mi*16 + g + half_*8;
                float2 v = make_float2(acc.a[mi][ni][half_*2] + bias.x,
                                       acc.a[mi][ni][half_*2+1] + bias.y);
                *(float2*)&out[(size_t)m*1024 + n] = v;
            }
        }
    }
}

// ---------------------------------------------------------------------------
// Flash attention, split-half: two independent 4-warp pipelines per CTA,
// each with private double-buffered KV smem and a named barrier, so the
// softmax scalar phases of the halves de-phase and overlap the other
// half's tensor work. Fixed-bias exp2 softmax, MMA row sums.
// smem: Q 32KB + 2 halves x 2 stages x 16KB = 96KB -> 2 CTAs/SM.
// ---------------------------------------------------------------------------
#define ASTG 16384
#define ATTN_SMEM_BYTES (2*16384 + 4*ASTG)   // 96KB

__device__ __forceinline__ void attn_issue_stage_h(uint32_t sbuf,
                                                   const __half* khp,
                                                   const __half* vhp,
                                                   int kt, int htid) {
    cp_tile64h(sbuf,        khp + (size_t)kt*DHn, htid);
    cp_tile64h(sbuf + 8192, vhp + (size_t)kt*DHn, htid);
}

__global__ __launch_bounds__(256, 2)
void attn_mma() {
    extern __shared__ char smem[];
    uint32_t sb = smem_u32(smem);
    const uint32_t sQh = sb;
    const uint32_t sQl = sQh + 16384;

    const int tid = threadIdx.x;
    const int w = tid >> 5, lane = tid & 31;
    const int g = lane >> 2, tg = lane & 3;
    const uint32_t lrow = lane & 15;
    const uint32_t lkhalf = (lane >> 4) * 16;

    const int h4 = w >> 2;               // half id (0/1)
    const int htid = tid & 127;          // thread id within half
    const int barid = 1 + h4;            // named barrier per half
    const uint32_t sKV = sb + 32768 + h4*(2*ASTG);   // this half's stages

    const int bh = blockIdx.y;
    const int b = bh >> 4, h = bh & 15;
    const int q0 = blockIdx.x * 128;

    const __half* qhp = g_qhi + ((size_t)bh*Qn + q0)*DHn;
    const __half* qlp = g_qlo + ((size_t)bh*Qn + q0)*DHn;
    const __half* khp = g_khi + (size_t)bh*Kn*DHn;
    const __half* vhp = g_vh  + (size_t)bh*Kn*DHn;

    // per-thread cp groups: g0 = Q, g1 = stage0 (own half), g2 = stage1
    cp_tile128(sQh, qhp, 128, tid);
    cp_tile128(sQl, qlp, 128, tid);
    CP_COMMIT();
    attn_issue_stage_h(sKV,        khp, vhp, 0,  htid);
    CP_COMMIT();
    attn_issue_stage_h(sKV + ASTG, khp, vhp, 64, htid);
    CP_COMMIT();

    CP_WAIT2();            // Q landed (for this thread)
    __syncthreads();       // full-CTA: Q visible to all

    uint32_t qh[4][4], ql[4][4];
    #pragma unroll
    for (int ks = 0; ks < 4; ks++) {
        uint32_t kb = ks*32 + lkhalf;
        uint32_t roff = SMEM_SWIZZLE_128B((uint32_t)((w*16 + lrow)*128) + kb);
        ldmx4(qh[ks], sQh + roff);
        ldmx4(ql[ks], sQl + roff);
    }

    float o[8][4];
    #pragma unroll
    for (int j = 0; j < 8; j++)
        #pragma unroll
        for (int c = 0; c < 4; c++) o[j][c] = 0.f;
    float lsum[4] = {0.f, 0.f, 0.f, 0.f};

    const int r0 = w*16 + g;
    const int r1 = r0 + 8;
    const uint32_t* mb0 = g_mbits + ((size_t)b*Qn + q0 + r0)*64;
    const uint32_t* mb1 = g_mbits + ((size_t)b*Qn + q0 + r1)*64;

    for (int it = 0; it < 32; it++) {
        CP_WAIT1();          // this half's stage it landed
        BARH(barid);

        const uint32_t sbuf = sKV + (it & 1)*ASTG;
        const uint32_t sKh = sbuf, sVh = sbuf + 8192;

        // S = Q K^T in log2 domain, biased
        float s[8][4];
        #pragma unroll
        for (int j = 0; j < 8; j++)
            #pragma unroll
            for (int c = 0; c < 4; c++) s[j][c] = ATTN_BIAS;

        #pragma unroll
        for (int ks = 0; ks < 4; ks++) {
            uint32_t kb = ks*32 + lkhalf;
            #pragma unroll
            for (int kg = 0; kg < 4; kg++) {
                uint32_t roff = SMEM_SWIZZLE_128B(
                    (uint32_t)((kg*16 + lrow)*128) + kb);
                uint32_t bh_[4];
                ldmx4(bh_, sKh + roff);
                #pragma unroll
                for (int s2 = 0; s2 < 2; s2++) {
                    int j = 2*kg + s2;
                    mma16816h(s[j], qh[ks], bh_[s2], bh_[s2+2]);
                    mma16816h(s[j], ql[ks], bh_[s2], bh_[s2+2]);
                }
            }
        }

        // mask, p = 2^s
        int kt = it * 64;
        uint2 mw0 = *(const uint2*)(mb0 + (kt >> 5));
        uint2 mw1 = *(const uint2*)(mb1 + (kt >> 5));
        #pragma unroll
        for (int j = 0; j < 8; j++) {
            int c = j*8 + tg*2;
            uint32_t w0 = (c & 32) ? mw0.y : mw0.x;
            uint32_t w1 = (c & 32) ? mw1.y : mw1.x;
            int sh = c & 31;
            s[j][0] = fexp2(((w0 >> sh) & 1u)     ? s[j][0] : MASK_FILL);
            s[j][1] = fexp2(((w0 >> (sh+1)) & 1u) ? s[j][1] : MASK_FILL);
            s[j][2] = fexp2(((w1 >> sh) & 1u)     ? s[j][2] : MASK_FILL);
            s[j][3] = fexp2(((w1 >> (sh+1)) & 1u) ? s[j][3] : MASK_FILL);
        }

        uint32_t pa[4][4];
        #pragma unroll
        for (int kk = 0; kk < 4; kk++) {
            pa[kk][0] = h2_as_u32(__floats2half2_rn(s[2*kk][0],   s[2*kk][1]));
            pa[kk][1] = h2_as_u32(__floats2half2_rn(s[2*kk][2],   s[2*kk][3]));
            pa[kk][2] = h2_as_u32(__floats2half2_rn(s[2*kk+1][0], s[2*kk+1][1]));
            pa[kk][3] = h2_as_u32(__floats2half2_rn(s[2*kk+1][2], s[2*kk+1][3]));
        }

        #pragma unroll
        for (int kk = 0; kk < 4; kk++) {
            mma16816h(lsum, pa[kk], ONES_H2, ONES_H2);
            #pragma unroll
            for (int dg = 0; dg < 4; dg++) {
                uint32_t vb[4];
                ldmx4t(vb, sVh + SMEM_SWIZZLE_128B(
                    (uint32_t)((kk*16 + lrow)*128 + dg*32) + lkhalf));
                mma16816h(o[2*dg],   pa[kk], vb[0], vb[1]);
                mma16816h(o[2*dg+1], pa[kk], vb[2], vb[3]);
            }
        }

        BARH(barid);         // half done with buffer (it&1)
        if (it + 2 < 32)
            attn_issue_stage_h(sKV + (it & 1)*ASTG, khp, vhp,
                               (it + 2)*64, htid);
        CP_COMMIT();
    }

    // lsum[0]/lsum[2] = row sums (replicated per quad)
    float inv0 = 1.f / fmaxf(lsum[0], 1e-30f);
    float inv1 = 1.f / fmaxf(lsum[2], 1e-30f);
    size_t i0 = ((size_t)(b*Qn + q0 + r0))*1024 + h*64;
    size_t i1 = ((size_t)(b*Qn + q0 + r1))*1024 + h*64;
    #pragma unroll
    for (int j = 0; j < 8; j++) {
        int d = j*8 + tg*2;
        float v0x = o[j][0]*inv0, v0y = o[j][1]*inv0;
        float v1x = o[j][2]*inv1, v1y = o[j][3]*inv1;
        __half h0x = __float2half_rn(v0x), h0y = __float2half_rn(v0y);
        __half h1x = __float2half_rn(v1x), h1y = __float2half_rn(v1y);
        __half l0x = __float2half_rn(v0x - __half2float(h0x));
        __half l0y = __float2half_rn(v0y - __half2float(h0y));
        __half l1x = __float2half_rn(v1x - __half2float(h1x));
        __half l1y = __float2half_rn(v1y - __half2float(h1y));
        *(__half2*)&g_ohi[i0 + d] = __halves2half2(h0x, h0y);
        *(__half2*)&g_olo[i0 + d] = __halves2half2(l0x, l0y);
        *(__half2*)&g_ohi[i1 + d] = __halves2half2(h1x, h1y);
        *(__half2*)&g_olo[i1 + d] = __halves2half2(l1x, l1y);
    }
}

// ---------------------------------------------------------------------------
extern "C" void kernel_launch(void* const* d_in, const int* in_sizes, int n_in,
                              void* d_out, int out_size)
{
    const float* x    = (const float*)d_in[0];
    const int*   mask = (const int*)d_in[1];
    const float* Wq   = (const float*)d_in[2];
    const float* Wk   = (const float*)d_in[3];
    const float* Wv   = (const float*)d_in[4];
    const float* Wo   = (const float*)d_in[5];
    const float* bo   = (const float*)d_in[6];
    float*       out  = (float*)d_out;

    cudaFuncSetAttribute(qkv_gemm_mma,
                         cudaFuncAttributeMaxDynamicSharedMemorySize, GEMM_SMEM_BYTES);
    cudaFuncSetAttribute(out_gemm_mma,
                         cudaFuncAttributeMaxDynamicSharedMemorySize, GEMM_SMEM_BYTES);
    cudaFuncSetAttribute(attn_mma,
                         cudaFuncAttributeMaxDynamicSharedMemorySize, ATTN_SMEM_BYTES);

    prep_all<<<14336, 256>>>(x, mask, Wq, Wk, Wv, Wo);

    qkv_gemm_mma<<<dim3(24, 64), 256, GEMM_SMEM_BYTES>>>();

    attn_mma<<<dim3(16, 64), 256, ATTN_SMEM_BYTES>>>();

    out_gemm_mma<<<dim3(8, 64), 256, GEMM_SMEM_BYTES>>>(bo, out);
}

// round 17
// speedup vs baseline: 1.0477x; 1.0477x over previous
#include <cuda_runtime.h>
#include <cuda_bf16.h>
#include <cuda_fp16.h>
#include <cstdint>

#define Bn  4
#define Qn  2048
#define Kn  2048
#define Dn  1024
#define Hn  16
#define DHn 64
#define BHn (Bn*Hn)

// Q pre-scale: 0.125 * log2(e)  (softmax scale + exp2-domain fold)
#define QSCALE 0.18033688011112042f
#define ATTN_BIAS (-4.0f)
#define MASK_FILL (-80.0f)
#define ONES_H2 0x3C003C00u

// ---------------------------------------------------------------------------
// Scratch (__device__ globals; cudaMalloc is forbidden)
// ---------------------------------------------------------------------------
__device__ __half g_qhi[(size_t)BHn*Qn*DHn];   // Q pre-scaled by QSCALE
__device__ __half g_qlo[(size_t)BHn*Qn*DHn];
__device__ __half g_khi[(size_t)BHn*Kn*DHn];   // K rounded (no lo)
__device__ __half g_vh [(size_t)BHn*Kn*DHn];

__device__ uint32_t g_mbits[(size_t)Bn*Qn*64];

__device__ __half g_xhi[(size_t)8192*1024];
__device__ __half g_xlo[(size_t)8192*1024];
__device__ __half g_ohi[(size_t)8192*1024];        // attn out split (b,q,h*64+d)
__device__ __half g_olo[(size_t)8192*1024];
__device__ __half g_wt [(size_t)3072*1024];        // W_{q,k,v}^T [n][k], fp16
__device__ __half g_wot[(size_t)1024*1024];        // Wo^T [n][k], fp16

// ---------------------------------------------------------------------------
// helpers
// ---------------------------------------------------------------------------
__device__ __forceinline__ uint32_t smem_u32(const void* p) {
    uint32_t a;
    asm("{ .reg .u64 t; cvta.to.shared.u64 t, %1; cvt.u32.u64 %0, t; }"
        : "=r"(a) : "l"(p));
    return a;
}
__device__ __forceinline__ uint32_t h2_as_u32(__half2 v) {
    return *reinterpret_cast<uint32_t*>(&v);
}

#define SMEM_SWIZZLE_128B(byte_offset) \
    ((byte_offset) ^ (((byte_offset) >> 3) & 0x70))

__device__ __forceinline__ void cp_async16(uint32_t s_dst, const void* g_src) {
    asm volatile("cp.async.cg.shared.global [%0], [%1], 16;"
                 :: "r"(s_dst), "l"(g_src));
}
#define CP_COMMIT()  asm volatile("cp.async.commit_group;" ::: "memory")
#define CP_WAIT1()   asm volatile("cp.async.wait_group 1;" ::: "memory")
#define CP_WAIT2()   asm volatile("cp.async.wait_group 2;" ::: "memory")

__device__ __forceinline__ void ldmx4(uint32_t* r, uint32_t addr) {
    asm volatile("ldmatrix.sync.aligned.m8n8.x4.shared.b16 {%0,%1,%2,%3}, [%4];"
                 : "=r"(r[0]), "=r"(r[1]), "=r"(r[2]), "=r"(r[3]) : "r"(addr));
}
__device__ __forceinline__ void ldmx4t(uint32_t* r, uint32_t addr) {
    asm volatile("ldmatrix.sync.aligned.m8n8.x4.trans.shared.b16 {%0,%1,%2,%3}, [%4];"
                 : "=r"(r[0]), "=r"(r[1]), "=r"(r[2]), "=r"(r[3]) : "r"(addr));
}

__device__ __forceinline__ void mma16816h(float* c, const uint32_t* a,
                                          uint32_t b0, uint32_t b1) {
    asm volatile(
        "mma.sync.aligned.m16n8k16.row.col.f32.f16.f16.f32 "
        "{%0,%1,%2,%3}, {%4,%5,%6,%7}, {%8,%9}, {%0,%1,%2,%3};"
        : "+f"(c[0]), "+f"(c[1]), "+f"(c[2]), "+f"(c[3])
        : "r"(a[0]), "r"(a[1]), "r"(a[2]), "r"(a[3]), "r"(b0), "r"(b1));
}

// fast exp2 (FFMA-only, rel err ~2.4e-6); caller guarantees t >= -80
__device__ __forceinline__ float fexp2(float t) {
    int i = __float2int_rn(t);
    float f = t - (float)i;
    float p = 1.3333558146e-3f;
    p = fmaf(p, f, 9.6181291057e-3f);
    p = fmaf(p, f, 5.5504108664e-2f);
    p = fmaf(p, f, 2.4022650696e-1f);
    p = fmaf(p, f, 6.9314718056e-1f);
    p = fmaf(p, f, 1.0f);
    return p * __int_as_float((i + 127) << 23);
}

// cp.async a 128-row x 128-byte tile into SW128 smem (256 threads)
__device__ __forceinline__ void cp_tile128(uint32_t s_dst, const void* gbase,
                                           size_t ld_bytes, int tid) {
    const char* g = (const char*)gbase;
    #pragma unroll
    for (int i = 0; i < 4; i++) {
        int f = tid + 256*i;
        int row = f >> 3;
        int c16 = f & 7;
        uint32_t off = SMEM_SWIZZLE_128B((uint32_t)(row*128 + c16*16));
        cp_async16(s_dst + off, g + (size_t)row*ld_bytes + c16*16);
    }
}

// ---------------------------------------------------------------------------
// Merged prep kernel: split x, transpose+round weights, pack mask bits.
// ---------------------------------------------------------------------------
__global__ void prep_all(const float* __restrict__ x,
                         const int*   __restrict__ mask,
                         const float* __restrict__ Wq,
                         const float* __restrict__ Wk,
                         const float* __restrict__ Wv,
                         const float* __restrict__ Wo) {
    int bx = blockIdx.x;
    if (bx < 8192) {
        size_t idx = ((size_t)bx * 256 + threadIdx.x) * 4;
        float4 v = *(const float4*)(x + idx);
        float a[4] = {v.x, v.y, v.z, v.w};
        __half h[4], l[4];
        #pragma unroll
        for (int i = 0; i < 4; i++) {
            h[i] = __float2half_rn(a[i]);
            l[i] = __float2half_rn(a[i] - __half2float(h[i]));
        }
        *(uint2*)(g_xhi + idx) = *(uint2*)h;
        *(uint2*)(g_xlo + idx) = *(uint2*)l;
    } else if (bx < 10240) {
        int warp = (bx - 8192) * 8 + (threadIdx.x >> 5);
        int lane = threadIdx.x & 31;
        size_t base = (size_t)warp * 1024;
        #pragma unroll 4
        for (int r = 0; r < 32; r++) {
            int v = mask[base + r*32 + lane];
            unsigned bits = __ballot_sync(0xffffffffu, v != 0);
            if (lane == 0) g_mbits[(size_t)warp*32 + r] = bits;
        }
    } else {
        __shared__ float T[32][33];
        int id = bx - 10240;
        int z = id >> 10;
        int rem = id & 1023;
        int n0 = (rem & 31) * 32, k0 = (rem >> 5) * 32;
        const float* src;
        __half* dh;
        if      (z == 0) { src = Wq; dh = g_wt; }
        else if (z == 1) { src = Wk; dh = g_wt + 1024*1024; }
        else if (z == 2) { src = Wv; dh = g_wt + 2048*1024; }
        else             { src = Wo; dh = g_wot; }
        int tx = threadIdx.x & 31, ty = threadIdx.x >> 5;
        #pragma unroll
        for (int i = 0; i < 4; i++)
            T[ty + 8*i][tx] = src[(size_t)(k0 + ty + 8*i) * 1024 + n0 + tx];
        __syncthreads();
        #pragma unroll
        for (int i = 0; i < 4; i++) {
            int n = n0 + ty + 8*i, k = k0 + tx;
            dh[(size_t)n*1024 + k] = __float2half_rn(T[tx][ty + 8*i]);
        }
    }
}

// ---------------------------------------------------------------------------
// mma.sync 2-product split-fp16 GEMM (R15-best, unchanged)
// ---------------------------------------------------------------------------
#define GSTG 49152
#define GEMM_SMEM_BYTES (2*GSTG)

struct GemmAcc { float a[4][4][4]; };

__device__ __forceinline__ void gemm_issue_stage(uint32_t sbuf,
                                                 const __half* Ahi,
                                                 const __half* Alo,
                                                 const __half* B,
                                                 int k0, int tid) {
    cp_tile128(sbuf,           Ahi + k0, 2048, tid);
    cp_tile128(sbuf + 16384,   Alo + k0, 2048, tid);
    cp_tile128(sbuf + 32768,   B   + k0, 2048, tid);
}

__device__ __forceinline__ void gemm_mainloop_mma(uint32_t sb, GemmAcc& A,
                                                  const __half* Ahi,
                                                  const __half* Alo,
                                                  const __half* B,
                                                  int tid) {
    const int wid  = tid >> 5, lane = tid & 31;
    const int mw   = wid & 1, nw = wid >> 1;
    const uint32_t lrow  = lane & 15;
    const uint32_t lkoff = (lane >> 4) * 16;

    #pragma unroll
    for (int mi = 0; mi < 4; mi++)
        #pragma unroll
        for (int ni = 0; ni < 4; ni++)
            #pragma unroll
            for (int j = 0; j < 4; j++) A.a[mi][ni][j] = 0.f;

    gemm_issue_stage(sb,        Ahi, Alo, B, 0,  tid);
    CP_COMMIT();
    gemm_issue_stage(sb + GSTG, Ahi, Alo, B, 64, tid);
    CP_COMMIT();

    for (int st = 0; st < 16; st++) {
        CP_WAIT1();
        __syncthreads();

        const uint32_t sbuf = sb + (st & 1)*GSTG;
        const uint32_t sAh = sbuf, sAl = sbuf + 16384, sB = sbuf + 32768;

        #pragma unroll
        for (int ks = 0; ks < 4; ks++) {
            const uint32_t kb = ks*32 + lkoff;

            uint32_t ah[4][4];
            #pragma unroll
            for (int mi = 0; mi < 4; mi++)
                ldmx4(ah[mi], sAh + SMEM_SWIZZLE_128B(
                      (uint32_t)((mw*64 + mi*16 + lrow)*128) + kb));
            uint32_t bh[2][4];
            #pragma unroll
            for (int np = 0; np < 2; np++)
                ldmx4(bh[np], sB + SMEM_SWIZZLE_128B(
                      (uint32_t)((nw*32 + np*16 + lrow)*128) + kb));

            #pragma unroll
            for (int mi = 0; mi < 4; mi++)
                #pragma unroll
                for (int ni = 0; ni < 4; ni++) {
                    int np = ni >> 1, s = ni & 1;
                    mma16816h(A.a[mi][ni], ah[mi], bh[np][s], bh[np][s+2]);
                }

            uint32_t al[4][4];
            #pragma unroll
            for (int mi = 0; mi < 4; mi++)
                ldmx4(al[mi], sAl + SMEM_SWIZZLE_128B(
                      (uint32_t)((mw*64 + mi*16 + lrow)*128) + kb));
            #pragma unroll
            for (int mi = 0; mi < 4; mi++)
                #pragma unroll
                for (int ni = 0; ni < 4; ni++) {
                    int np = ni >> 1, s = ni & 1;
                    mma16816h(A.a[mi][ni], al[mi], bh[np][s], bh[np][s+2]);
                }
        }
        __syncthreads();

        if (st + 2 < 16)
            gemm_issue_stage(sb + (st & 1)*GSTG, Ahi, Alo, B, (st + 2)*64, tid);
        CP_COMMIT();
    }
}

__global__ __launch_bounds__(256, 2)
void qkv_gemm_mma() {
    extern __shared__ char smem[];
    uint32_t sb = smem_u32(smem);
    int tid = threadIdx.x, lane = tid & 31, wid = tid >> 5;
    int mw = wid & 1, nw = wid >> 1;
    int n_base = blockIdx.x * 128;
    int m0 = blockIdx.y * 128;

    int kind;                      // 0=Q (scaled, hi/lo), 1=K (rounded), 2=V
    if      (n_base < 1024) kind = 0;
    else if (n_base < 2048) kind = 1;
    else                    kind = 2;

    GemmAcc acc;
    gemm_mainloop_mma(sb, acc,
                      g_xhi + (size_t)m0*1024, g_xlo + (size_t)m0*1024,
                      g_wt + (size_t)n_base*1024, tid);

    int col_base = n_base & 1023;
    int g = lane >> 2, tg = lane & 3;
    #pragma unroll
    for (int mi = 0; mi < 4; mi++) {
        #pragma unroll
        for (int ni = 0; ni < 4; ni++) {
            int col = col_base + nw*32 + ni*8 + tg*2;
            int h = col >> 6, d = col & 63;
            #pragma unroll
            for (int half_ = 0; half_ < 2; half_++) {
                int m = m0 + mw*64 + mi*16 + g + half_*8;
                int bb = m >> 11, qp = m & 2047;
                float vx = acc.a[mi][ni][half_*2];
                float vy = acc.a[mi][ni][half_*2+1];
                size_t idx = (((size_t)(bb*Hn + h))*Qn + qp)*DHn + d;
                if (kind == 0) {
                    vx *= QSCALE; vy *= QSCALE;
                    __half hx = __float2half_rn(vx), hy = __float2half_rn(vy);
                    __half lx = __float2half_rn(vx - __half2float(hx));
                    __half ly = __float2half_rn(vy - __half2float(hy));
                    *(__half2*)&g_qhi[idx] = __halves2half2(hx, hy);
                    *(__half2*)&g_qlo[idx] = __halves2half2(lx, ly);
                } else {
                    __half2 hh = __halves2half2(__float2half_rn(vx),
                                                __float2half_rn(vy));
                    if (kind == 2) *(__half2*)&g_vh[idx]  = hh;
                    else           *(__half2*)&g_khi[idx] = hh;
                }
            }
        }
    }
}

__global__ __launch_bounds__(256, 2)
void out_gemm_mma(const float* __restrict__ bo, float* __restrict__ out) {
    extern __shared__ char smem[];
    uint32_t sb = smem_u32(smem);
    int tid = threadIdx.x, lane = tid & 31, wid = tid >> 5;
    int mw = wid & 1, nw = wid >> 1;
    int n_base = blockIdx.x * 128;
    int m0 = blockIdx.y * 128;

    GemmAcc acc;
    gemm_mainloop_mma(sb, acc,
                      g_ohi + (size_t)m0*1024, g_olo + (size_t)m0*1024,
                      g_wot + (size_t)n_base*1024, tid);

    int g = lane >> 2, tg = lane & 3;
    #pragma unroll
    for (int ni = 0; ni < 4; ni++) {
        int n = n_base + nw*32 + ni*8 + tg*2;
        float2 bias = *(const float2*)&bo[n];
        #pragma unroll
        for (int mi = 0; mi < 4; mi++) {
            #pragma unroll
            for (int half_ = 0; half_ < 2; half_++) {
                int m = m0 + mw*64 + mi*16 + g + half_*8;
                float2 v = make_float2(acc.a[mi][ni][half_*2] + bias.x,
                                       acc.a[mi][ni][half_*2+1] + bias.y);
                *(float2*)&out[(size_t)m*1024 + n] = v;
            }
        }
    }
}

// ---------------------------------------------------------------------------
// Flash attention: single pipeline (R15 structure), KV tile = 128 keys
// per iteration processed as two 64-key subtiles -> half the barriers.
// Fixed-bias exp2 softmax, MMA row sums, fused fp16 hi/lo epilogue.
// smem: Q 32KB + 2 stages x 32KB = 96KB -> 2 CTAs/SM.
// ---------------------------------------------------------------------------
#define ASTG 32768    // Kh(16K) + Vh(16K) per 128-key stage
#define ATTN_SMEM_BYTES (2*16384 + 2*ASTG)   // 96KB

__device__ __forceinline__ void attn_issue_stage(uint32_t sbuf,
                                                 const __half* khp,
                                                 const __half* vhp,
                                                 int kt, int tid) {
    cp_tile128(sbuf,         khp + (size_t)kt*DHn, 128, tid);
    cp_tile128(sbuf + 16384, vhp + (size_t)kt*DHn, 128, tid);
}

__global__ __launch_bounds__(256, 2)
void attn_mma() {
    extern __shared__ char smem[];
    uint32_t sb = smem_u32(smem);
    const uint32_t sQh = sb;
    const uint32_t sQl = sQh + 16384;
    const uint32_t sKV = sQl + 16384;     // two 32KB stages

    const int tid = threadIdx.x;
    const int w = tid >> 5, lane = tid & 31;
    const int g = lane >> 2, tg = lane & 3;
    const uint32_t lrow = lane & 15;
    const uint32_t lkhalf = (lane >> 4) * 16;

    const int bh = blockIdx.y;
    const int b = bh >> 4, h = bh & 15;
    const int q0 = blockIdx.x * 128;

    const __half* qhp = g_qhi + ((size_t)bh*Qn + q0)*DHn;
    const __half* qlp = g_qlo + ((size_t)bh*Qn + q0)*DHn;
    const __half* khp = g_khi + (size_t)bh*Kn*DHn;
    const __half* vhp = g_vh  + (size_t)bh*Kn*DHn;

    // g0: Q; g1: KV stage0 (keys 0..127); g2: KV stage1 (keys 128..255)
    cp_tile128(sQh, qhp, 128, tid);
    cp_tile128(sQl, qlp, 128, tid);
    CP_COMMIT();
    attn_issue_stage(sKV,        khp, vhp, 0,   tid);
    CP_COMMIT();
    attn_issue_stage(sKV + ASTG, khp, vhp, 128, tid);
    CP_COMMIT();

    CP_WAIT2();
    __syncthreads();

    uint32_t qh[4][4], ql[4][4];
    #pragma unroll
    for (int ks = 0; ks < 4; ks++) {
        uint32_t kb = ks*32 + lkhalf;
        uint32_t roff = SMEM_SWIZZLE_128B((uint32_t)((w*16 + lrow)*128) + kb);
        ldmx4(qh[ks], sQh + roff);
        ldmx4(ql[ks], sQl + roff);
    }

    float o[8][4];
    #pragma unroll
    for (int j = 0; j < 8; j++)
        #pragma unroll
        for (int c = 0; c < 4; c++) o[j][c] = 0.f;
    float lsum[4] = {0.f, 0.f, 0.f, 0.f};

    const int r0 = w*16 + g;
    const int r1 = r0 + 8;
    const uint32_t* mb0 = g_mbits + ((size_t)b*Qn + q0 + r0)*64;
    const uint32_t* mb1 = g_mbits + ((size_t)b*Qn + q0 + r1)*64;

    for (int it = 0; it < 16; it++) {
        CP_WAIT1();           // 128-key stage it landed
        __syncthreads();

        const uint32_t stg = sKV + (it & 1)*ASTG;

        #pragma unroll
        for (int sub = 0; sub < 2; sub++) {
            const uint32_t sKh = stg + sub*8192;
            const uint32_t sVh = stg + 16384 + sub*8192;

            // S = Q K^T in log2 domain, biased
            float s[8][4];
            #pragma unroll
            for (int j = 0; j < 8; j++)
                #pragma unroll
                for (int c = 0; c < 4; c++) s[j][c] = ATTN_BIAS;

            #pragma unroll
            for (int ks = 0; ks < 4; ks++) {
                uint32_t kb = ks*32 + lkhalf;
                #pragma unroll
                for (int kg = 0; kg < 4; kg++) {
                    uint32_t roff = SMEM_SWIZZLE_128B(
                        (uint32_t)((kg*16 + lrow)*128) + kb);
                    uint32_t bh_[4];
                    ldmx4(bh_, sKh + roff);
                    #pragma unroll
                    for (int s2 = 0; s2 < 2; s2++) {
                        int j = 2*kg + s2;
                        mma16816h(s[j], qh[ks], bh_[s2], bh_[s2+2]);
                        mma16816h(s[j], ql[ks], bh_[s2], bh_[s2+2]);
                    }
                }
            }

            // mask, p = 2^s
            int kt = it * 128 + sub * 64;
            uint2 mw0 = *(const uint2*)(mb0 + (kt >> 5));
            uint2 mw1 = *(const uint2*)(mb1 + (kt >> 5));
            #pragma unroll
            for (int j = 0; j < 8; j++) {
                int c = j*8 + tg*2;
                uint32_t w0 = (c & 32) ? mw0.y : mw0.x;
                uint32_t w1 = (c & 32) ? mw1.y : mw1.x;
                int sh = c & 31;
                s[j][0] = fexp2(((w0 >> sh) & 1u)     ? s[j][0] : MASK_FILL);
                s[j][1] = fexp2(((w0 >> (sh+1)) & 1u) ? s[j][1] : MASK_FILL);
                s[j][2] = fexp2(((w1 >> sh) & 1u)     ? s[j][2] : MASK_FILL);
                s[j][3] = fexp2(((w1 >> (sh+1)) & 1u) ? s[j][3] : MASK_FILL);
            }

            uint32_t pa[4][4];
            #pragma unroll
            for (int kk = 0; kk < 4; kk++) {
                pa[kk][0] = h2_as_u32(__floats2half2_rn(s[2*kk][0],   s[2*kk][1]));
                pa[kk][1] = h2_as_u32(__floats2half2_rn(s[2*kk][2],   s[2*kk][3]));
                pa[kk][2] = h2_as_u32(__floats2half2_rn(s[2*kk+1][0], s[2*kk+1][1]));
                pa[kk][3] = h2_as_u32(__floats2half2_rn(s[2*kk+1][2], s[2*kk+1][3]));
            }

            #pragma unroll
            for (int kk = 0; kk < 4; kk++) {
                mma16816h(lsum, pa[kk], ONES_H2, ONES_H2);
                #pragma unroll
                for (int dg = 0; dg < 4; dg++) {
                    uint32_t vb[4];
                    ldmx4t(vb, sVh + SMEM_SWIZZLE_128B(
                        (uint32_t)((kk*16 + lrow)*128 + dg*32) + lkhalf));
                    mma16816h(o[2*dg],   pa[kk], vb[0], vb[1]);
                    mma16816h(o[2*dg+1], pa[kk], vb[2], vb[3]);
                }
            }
        }
        __syncthreads();

        if (it + 2 < 16)
            attn_issue_stage(sKV + (it & 1)*ASTG, khp, vhp, (it + 2)*128, tid);
        CP_COMMIT();
    }

    // lsum[0]/lsum[2] = row sums (replicated per quad)
    float inv0 = 1.f / fmaxf(lsum[0], 1e-30f);
    float inv1 = 1.f / fmaxf(lsum[2], 1e-30f);
    size_t i0 = ((size_t)(b*Qn + q0 + r0))*1024 + h*64;
    size_t i1 = ((size_t)(b*Qn + q0 + r1))*1024 + h*64;
    #pragma unroll
    for (int j = 0; j < 8; j++) {
        int d = j*8 + tg*2;
        float v0x = o[j][0]*inv0, v0y = o[j][1]*inv0;
        float v1x = o[j][2]*inv1, v1y = o[j][3]*inv1;
        __half h0x = __float2half_rn(v0x), h0y = __float2half_rn(v0y);
        __half h1x = __float2half_rn(v1x), h1y = __float2half_rn(v1y);
        __half l0x = __float2half_rn(v0x - __half2float(h0x));
        __half l0y = __float2half_rn(v0y - __half2float(h0y));
        __half l1x = __float2half_rn(v1x - __half2float(h1x));
        __half l1y = __float2half_rn(v1y - __half2float(h1y));
        *(__half2*)&g_ohi[i0 + d] = __halves2half2(h0x, h0y);
        *(__half2*)&g_olo[i0 + d] = __halves2half2(l0x, l0y);
        *(__half2*)&g_ohi[i1 + d] = __halves2half2(h1x, h1y);
        *(__half2*)&g_olo[i1 + d] = __halves2half2(l1x, l1y);
    }
}

// ---------------------------------------------------------------------------
extern "C" void kernel_launch(void* const* d_in, const int* in_sizes, int n_in,
                              void* d_out, int out_size)
{
    const float* x    = (const float*)d_in[0];
    const int*   mask = (const int*)d_in[1];
    const float* Wq   = (const float*)d_in[2];
    const float* Wk   = (const float*)d_in[3];
    const float* Wv   = (const float*)d_in[4];
    const float* Wo   = (const float*)d_in[5];
    const float* bo   = (const float*)d_in[6];
    float*       out  = (float*)d_out;

    cudaFuncSetAttribute(qkv_gemm_mma,
                         cudaFuncAttributeMaxDynamicSharedMemorySize, GEMM_SMEM_BYTES);
    cudaFuncSetAttribute(out_gemm_mma,
                         cudaFuncAttributeMaxDynamicSharedMemorySize, GEMM_SMEM_BYTES);
    cudaFuncSetAttribute(attn_mma,
                         cudaFuncAttributeMaxDynamicSharedMemorySize, ATTN_SMEM_BYTES);

    prep_all<<<14336, 256>>>(x, mask, Wq, Wk, Wv, Wo);

    qkv_gemm_mma<<<dim3(24, 64), 256, GEMM_SMEM_BYTES>>>();

    attn_mma<<<dim3(16, 64), 256, ATTN_SMEM_BYTES>>>();

    out_gemm_mma<<<dim3(8, 64), 256, GEMM_SMEM_BYTES>>>(bo, out);
}